// round 1
// baseline (speedup 1.0000x reference)
#include <cuda_runtime.h>
#include <math.h>

// Problem constants
#define PIXELS 8192      // B*H*W = 8*32*32
#define DD 512
#define FF 32
#define NN 16384
#define HWSZ 1024
#define SPLITS 8
#define CPS (NN / SPLITS)   // 2048 codes per split

// Output layout (concatenated flattened outputs, float32):
// [0, 4194304)            out   [8,512,32,32]
// [4194304, 4202496)      closest [8,32,32] as float
// [4202496]               loss_q
// [4202497]               perplexity
#define OUT_OFF      0
#define CLOSEST_OFF  4194304
#define LOSS_OFF     4202496
#define PERP_OFF     4202497

// Scratch (no allocations allowed)
__device__ float g_xn[PIXELS * FF];       // normalized projected x, [p][32]
__device__ float g_en[NN * FF];           // normalized codebook, [n][32]
__device__ float g_pval[SPLITS * PIXELS]; // per-split best value
__device__ int   g_pidx[SPLITS * PIXELS]; // per-split best index
__device__ int   g_closest[PIXELS];
__device__ int   g_hist[NN];
__device__ float g_lossp[PIXELS];

// ---------------------------------------------------------------------------
// Kernel A: 1x1 conv projection + channel L2 normalize.
// Block = 256 threads, 32 pixels per block, full proj_w (64KB) in dyn smem.
// thread (lane=pixel, fg=f-group of 4)
// ---------------------------------------------------------------------------
__global__ void proj_norm_kernel(const float* __restrict__ enc,
                                 const float* __restrict__ pw,
                                 const float* __restrict__ pb)
{
    extern __shared__ float sm[];
    float* Ws  = sm;                 // 32*512
    float* xsh = sm + FF * DD;       // 32*33 (padded)
    float* nrm = xsh + 32 * 33;      // 32

    int tid = threadIdx.x;

    // stage proj_w [32][512] into shared (16384 floats)
    const float4* W4 = (const float4*)pw;
    float4* Ws4 = (float4*)Ws;
#pragma unroll
    for (int i = 0; i < 16; i++) Ws4[tid + 256 * i] = W4[tid + 256 * i];
    __syncthreads();

    int lane = tid & 31;     // pixel within tile
    int fg   = tid >> 5;     // 0..7
    int f0   = fg * 4;
    int p    = blockIdx.x * 32 + lane;
    int b    = p >> 10;
    int hw   = p & 1023;

    const float* ep = enc + (size_t)b * DD * HWSZ + hw;
    const float4* w0 = (const float4*)(Ws + (size_t)(f0 + 0) * DD);
    const float4* w1 = (const float4*)(Ws + (size_t)(f0 + 1) * DD);
    const float4* w2 = (const float4*)(Ws + (size_t)(f0 + 2) * DD);
    const float4* w3 = (const float4*)(Ws + (size_t)(f0 + 3) * DD);

    float a0 = 0.f, a1 = 0.f, a2 = 0.f, a3 = 0.f;
#pragma unroll 4
    for (int q = 0; q < 128; q++) {
        float e0 = ep[(4 * q + 0) * HWSZ];
        float e1 = ep[(4 * q + 1) * HWSZ];
        float e2 = ep[(4 * q + 2) * HWSZ];
        float e3 = ep[(4 * q + 3) * HWSZ];
        float4 W0 = w0[q], W1 = w1[q], W2 = w2[q], W3 = w3[q];
        a0 += e0 * W0.x; a0 += e1 * W0.y; a0 += e2 * W0.z; a0 += e3 * W0.w;
        a1 += e0 * W1.x; a1 += e1 * W1.y; a1 += e2 * W1.z; a1 += e3 * W1.w;
        a2 += e0 * W2.x; a2 += e1 * W2.y; a2 += e2 * W2.z; a2 += e3 * W2.w;
        a3 += e0 * W3.x; a3 += e1 * W3.y; a3 += e2 * W3.z; a3 += e3 * W3.w;
    }
    a0 += pb[f0 + 0];
    a1 += pb[f0 + 1];
    a2 += pb[f0 + 2];
    a3 += pb[f0 + 3];

    xsh[lane * 33 + f0 + 0] = a0;
    xsh[lane * 33 + f0 + 1] = a1;
    xsh[lane * 33 + f0 + 2] = a2;
    xsh[lane * 33 + f0 + 3] = a3;
    __syncthreads();

    if (tid < 32) {
        float ss = 0.f;
#pragma unroll
        for (int f = 0; f < 32; f++) { float v = xsh[tid * 33 + f]; ss += v * v; }
        nrm[tid] = fmaxf(sqrtf(ss), 1e-6f);
    }
    __syncthreads();

    float nm = nrm[lane];
    float4 o;
    o.x = a0 / nm; o.y = a1 / nm; o.z = a2 / nm; o.w = a3 / nm;
    *(float4*)(g_xn + (size_t)p * FF + f0) = o;
}

// ---------------------------------------------------------------------------
// Kernel B: codebook L2 normalize (warp per row) + zero histogram.
// grid 2048 x 256 threads
// ---------------------------------------------------------------------------
__global__ void enorm_kernel(const float* __restrict__ emb)
{
    int tid  = threadIdx.x;
    int r    = blockIdx.x * 8 + (tid >> 5);
    int lane = tid & 31;
    float v = emb[(size_t)r * 32 + lane];
    float ss = v * v;
#pragma unroll
    for (int o = 16; o; o >>= 1) ss += __shfl_xor_sync(0xffffffffu, ss, o);
    float nm = fmaxf(sqrtf(ss), 1e-6f);
    g_en[(size_t)r * 32 + lane] = v / nm;
    if (tid < 8) g_hist[blockIdx.x * 8 + tid] = 0;
}

// ---------------------------------------------------------------------------
// Kernel C (dominant): fused cosine-sims GEMM + running argmax.
// Block: 256 threads (16 tx codes x 16 ty pixels), 128-pixel tile,
// iterates its split's 2048 codes in chunks of 128. 8x8 register tile.
// grid (64 pixel tiles, 8 code splits)
// ---------------------------------------------------------------------------
__global__ void __launch_bounds__(256, 2) sims_argmax_kernel()
{
    __shared__ float xs[128 * 33];   // x tile, padded rows
    __shared__ float es[32 * 132];   // e tile transposed [f][c], padded rows

    int tid   = threadIdx.x;
    int px0   = blockIdx.x * 128;
    int cbase = blockIdx.y * CPS;

    // load x tile (128 pixels x 32 f)
    for (int i = tid; i < 1024; i += 256) {
        int pp = i >> 3;
        int f0 = (i & 7) * 4;
        float4 v = *(const float4*)(g_xn + (size_t)(px0 + pp) * 32 + f0);
        xs[pp * 33 + f0 + 0] = v.x;
        xs[pp * 33 + f0 + 1] = v.y;
        xs[pp * 33 + f0 + 2] = v.z;
        xs[pp * 33 + f0 + 3] = v.w;
    }

    int tx = tid & 15;
    int ty = tid >> 4;
    float bv[8];
    int   bi[8];
#pragma unroll
    for (int i = 0; i < 8; i++) { bv[i] = -3.4e38f; bi[i] = 0; }

    int c_loc = tid & 127;
    int fhalf = (tid >> 7) * 4;   // 0 or 4

    for (int ch = 0; ch < CPS; ch += 128) {
        __syncthreads();
        // load e chunk transposed: es[f][c] = e_norm[cbase+ch+c][f]
#pragma unroll
        for (int k = 0; k < 4; k++) {
            int f0 = (fhalf + k) * 4;
            float4 v = *(const float4*)(g_en + (size_t)(cbase + ch + c_loc) * 32 + f0);
            es[(f0 + 0) * 132 + c_loc] = v.x;
            es[(f0 + 1) * 132 + c_loc] = v.y;
            es[(f0 + 2) * 132 + c_loc] = v.z;
            es[(f0 + 3) * 132 + c_loc] = v.w;
        }
        __syncthreads();

        float acc[8][8];
#pragma unroll
        for (int i = 0; i < 8; i++)
#pragma unroll
            for (int j = 0; j < 8; j++) acc[i][j] = 0.f;

#pragma unroll 4
        for (int f = 0; f < 32; f++) {
            float xv[8], ev[8];
#pragma unroll
            for (int i = 0; i < 8; i++) xv[i] = xs[(ty * 8 + i) * 33 + f];
#pragma unroll
            for (int j = 0; j < 8; j++) ev[j] = es[f * 132 + tx + 16 * j];
#pragma unroll
            for (int i = 0; i < 8; i++)
#pragma unroll
                for (int j = 0; j < 8; j++)
                    acc[i][j] += xv[i] * ev[j];
        }

        // argmax update; j ascending -> code index ascending (strict > keeps
        // first occurrence, matching jnp.argmax tie-break within this thread)
#pragma unroll
        for (int j = 0; j < 8; j++) {
            int cg = cbase + ch + tx + 16 * j;
#pragma unroll
            for (int i = 0; i < 8; i++) {
                float v = acc[i][j];
                if (v > bv[i]) { bv[i] = v; bi[i] = cg; }
            }
        }
    }

    // cross-tx reduction in shared (reuse es buffer)
    __syncthreads();
    float* rv = es;                  // [128][16] floats
    int*   ri = (int*)(es + 2048);   // [128][16] ints
#pragma unroll
    for (int i = 0; i < 8; i++) {
        rv[(ty * 8 + i) * 16 + tx] = bv[i];
        ri[(ty * 8 + i) * 16 + tx] = bi[i];
    }
    __syncthreads();
    if (tid < 128) {
        float v = -3.4e38f;
        int ix = 0x7fffffff;
#pragma unroll
        for (int k = 0; k < 16; k++) {
            float vv = rv[tid * 16 + k];
            int   ii = ri[tid * 16 + k];
            if (vv > v || (vv == v && ii < ix)) { v = vv; ix = ii; }
        }
        g_pval[blockIdx.y * PIXELS + px0 + tid] = v;
        g_pidx[blockIdx.y * PIXELS + px0 + tid] = ix;
    }
}

// ---------------------------------------------------------------------------
// Kernel F: reduce split partials -> closest; histogram; per-pixel loss partial.
// grid 32 x 256
// ---------------------------------------------------------------------------
__global__ void reduce_kernel(float* __restrict__ out)
{
    int p = blockIdx.x * 256 + threadIdx.x;
    float bv = -3.4e38f;
    int   bi = 0x7fffffff;
#pragma unroll
    for (int s = 0; s < SPLITS; s++) {
        float v = g_pval[s * PIXELS + p];
        int  ix = g_pidx[s * PIXELS + p];
        if (v > bv || (v == bv && ix < bi)) { bv = v; bi = ix; }
    }
    g_closest[p] = bi;
    out[CLOSEST_OFF + p] = (float)bi;
    atomicAdd(&g_hist[bi], 1);

    float s2 = 0.f;
    const float4* xr = (const float4*)(g_xn + (size_t)p * 32);
    const float4* er = (const float4*)(g_en + (size_t)bi * 32);
#pragma unroll
    for (int q = 0; q < 8; q++) {
        float4 x = xr[q], e = er[q];
        float d0 = x.x - e.x, d1 = x.y - e.y, d2 = x.z - e.z, d3 = x.w - e.w;
        s2 += d0 * d0; s2 += d1 * d1; s2 += d2 * d2; s2 += d3 * d3;
    }
    g_lossp[p] = s2;
}

// ---------------------------------------------------------------------------
// Kernel D: expansion GEMM: out[b,d,hw] = sum_f lat[p][f] * exp_w[d][f] + exp_b[d]
// grid (32 pixel blocks, 8 d-chunks of 64), 256 threads (one pixel each)
// ---------------------------------------------------------------------------
__global__ void expand_kernel(const float* __restrict__ ew,
                              const float* __restrict__ eb,
                              float* __restrict__ out)
{
    __shared__ float Wsh[64 * 32];
    __shared__ float bsh[64];
    int tid = threadIdx.x;
    int d0  = blockIdx.y * 64;

    const float4* src = (const float4*)(ew + (size_t)d0 * 32);
    float4* dst = (float4*)Wsh;
    dst[tid]       = src[tid];
    dst[tid + 256] = src[tid + 256];
    if (tid < 64) bsh[tid] = eb[d0 + tid];
    __syncthreads();

    int p  = blockIdx.x * 256 + tid;
    int b  = p >> 10;
    int hw = p & 1023;
    int idx = g_closest[p];

    float4 lat[8];
    const float4* lr = (const float4*)(g_en + (size_t)idx * 32);
#pragma unroll
    for (int q = 0; q < 8; q++) lat[q] = lr[q];

    float* outp = out + OUT_OFF + ((size_t)b * 512 + d0) * 1024 + hw;
#pragma unroll 2
    for (int dd = 0; dd < 64; dd++) {
        const float4* wr = (const float4*)(Wsh + dd * 32);
        float s = bsh[dd];
#pragma unroll
        for (int q = 0; q < 8; q++) {
            float4 w = wr[q];
            s += lat[q].x * w.x; s += lat[q].y * w.y;
            s += lat[q].z * w.z; s += lat[q].w * w.w;
        }
        outp[(size_t)dd * 1024] = s;
    }
}

// ---------------------------------------------------------------------------
// Kernel G: deterministic final reductions -> loss_q, perplexity
// single block
// ---------------------------------------------------------------------------
__global__ void finalize_kernel(float* __restrict__ out)
{
    __shared__ double sh[256];
    int tid = threadIdx.x;

    double ls = 0.0;
    for (int i = tid; i < PIXELS; i += 256) ls += (double)g_lossp[i];
    sh[tid] = ls;
    __syncthreads();
    for (int o = 128; o; o >>= 1) {
        if (tid < o) sh[tid] += sh[tid + o];
        __syncthreads();
    }
    double loss = sh[0] / (double)(PIXELS * 32);
    __syncthreads();

    double ps = 0.0;
    for (int i = tid; i < NN; i += 256) {
        float u = (float)g_hist[i] * (1.0f / 8192.0f);
        ps += -(double)u * log((double)u + 1e-6);
    }
    sh[tid] = ps;
    __syncthreads();
    for (int o = 128; o; o >>= 1) {
        if (tid < o) sh[tid] += sh[tid + o];
        __syncthreads();
    }
    if (tid == 0) {
        out[LOSS_OFF] = (float)loss;
        out[PERP_OFF] = (float)exp(sh[0]);
    }
}

// ---------------------------------------------------------------------------
extern "C" void kernel_launch(void* const* d_in, const int* in_sizes, int n_in,
                              void* d_out, int out_size)
{
    const float* enc = (const float*)d_in[0];  // [8,512,32,32]
    const float* emb = (const float*)d_in[1];  // [16384,32]
    const float* pw  = (const float*)d_in[2];  // [32,512]
    const float* pb  = (const float*)d_in[3];  // [32]
    const float* ew  = (const float*)d_in[4];  // [512,32]
    const float* eb  = (const float*)d_in[5];  // [512]
    float* out = (float*)d_out;

    (void)in_sizes; (void)n_in; (void)out_size;

    const int a_smem = (FF * DD + 32 * 33 + 32) * (int)sizeof(float); // 69888
    cudaFuncSetAttribute(proj_norm_kernel,
                         cudaFuncAttributeMaxDynamicSharedMemorySize, a_smem);

    proj_norm_kernel<<<256, 256, a_smem>>>(enc, pw, pb);
    enorm_kernel<<<2048, 256>>>(emb);
    sims_argmax_kernel<<<dim3(64, SPLITS), 256>>>();
    reduce_kernel<<<32, 256>>>(out);
    expand_kernel<<<dim3(32, 8), 256>>>(ew, eb, out);
    finalize_kernel<<<1, 256>>>(out);
}